// round 2
// baseline (speedup 1.0000x reference)
#include <cuda_runtime.h>
#include <cuda_bf16.h>
#include <cstdint>

#define ROW_LEN 4096
#define THREADS 256
#define V4 4              // float4 per thread per row: 4096/4/256
#define ROWS_PER_CTA 4

__device__ __forceinline__ void load_row(const float4* __restrict__ xr, int t, float4 v[V4])
{
#pragma unroll
    for (int k = 0; k < V4; ++k)
        v[k] = __ldcs(&xr[t + k * THREADS]);
}

__device__ __forceinline__ void process_row(float4 v[V4], float4* __restrict__ outr, int t,
                                            float* smn, float* smx, float* s_sz)
{
    // local min/max over 16 values
    float mn = v[0].x, mx = v[0].x;
#pragma unroll
    for (int k = 0; k < V4; ++k) {
        mn = fminf(mn, fminf(fminf(v[k].x, v[k].y), fminf(v[k].z, v[k].w)));
        mx = fmaxf(mx, fmaxf(fmaxf(v[k].x, v[k].y), fmaxf(v[k].z, v[k].w)));
    }
    // warp reduce
#pragma unroll
    for (int off = 16; off > 0; off >>= 1) {
        mn = fminf(mn, __shfl_xor_sync(0xFFFFFFFFu, mn, off));
        mx = fmaxf(mx, __shfl_xor_sync(0xFFFFFFFFu, mx, off));
    }
    const int wid = t >> 5, lid = t & 31;
    if (lid == 0) { smn[wid] = mn; smx[wid] = mx; }
    __syncthreads();
    if (t == 0) {
        float bmn = smn[0], bmx = smx[0];
#pragma unroll
        for (int i = 1; i < 8; ++i) {
            bmn = fminf(bmn, smn[i]);
            bmx = fmaxf(bmx, smx[i]);
        }
        float scale = (bmx - bmn) * (1.0f / 255.0f);
        scale = fminf(fmaxf(scale, 1e-5f), 1e4f);
        float zp = -bmn / scale;
        zp = fminf(fmaxf(zp, -1e4f), 1e4f);
        s_sz[0] = scale;
        s_sz[1] = zp;
    }
    __syncthreads();

    const float scale = s_sz[0];
    const float zp    = s_sz[1];
    const float inv   = 1.0f / scale;

#pragma unroll
    for (int k = 0; k < V4; ++k) {
        float4 r;
        float q;
        q = rintf(v[k].x * inv) + zp; q = fminf(fmaxf(q, 0.0f), 255.0f); r.x = (q - zp) * scale;
        q = rintf(v[k].y * inv) + zp; q = fminf(fmaxf(q, 0.0f), 255.0f); r.y = (q - zp) * scale;
        q = rintf(v[k].z * inv) + zp; q = fminf(fmaxf(q, 0.0f), 255.0f); r.z = (q - zp) * scale;
        q = rintf(v[k].w * inv) + zp; q = fminf(fmaxf(q, 0.0f), 255.0f); r.w = (q - zp) * scale;
        __stcs(&outr[t + k * THREADS], r);
    }
    __syncthreads();   // protect smem reuse for next row
}

__global__ void __launch_bounds__(THREADS, 5)
quant_rowwise_pipelined(const float* __restrict__ x, float* __restrict__ out)
{
    __shared__ float smn[8], smx[8];
    __shared__ float s_sz[2];

    const int t = threadIdx.x;
    const size_t row0 = (size_t)blockIdx.x * ROWS_PER_CTA;

    const float4* xr0  = reinterpret_cast<const float4*>(x   + row0 * ROW_LEN);
    float4*       or0  = reinterpret_cast<float4*>(out + row0 * ROW_LEN);
    const int V4_ROW = ROW_LEN / 4;

    float4 a[V4], b[V4];

    // prologue: load row 0
    load_row(xr0, t, a);

#pragma unroll
    for (int r = 0; r < ROWS_PER_CTA; ++r) {
        float4* cur = (r & 1) ? b : a;
        float4* nxt = (r & 1) ? a : b;
        // prefetch next row BEFORE the reduce of the current row:
        // these LDGs fill the reduce/barrier/store window.
        if (r + 1 < ROWS_PER_CTA)
            load_row(xr0 + (size_t)(r + 1) * V4_ROW, t, nxt);
        process_row(cur, or0 + (size_t)r * V4_ROW, t, smn, smx, s_sz);
    }
}

extern "C" void kernel_launch(void* const* d_in, const int* in_sizes, int n_in,
                              void* d_out, int out_size)
{
    const float* x = (const float*)d_in[0];
    float* out = (float*)d_out;
    const int n_rows = in_sizes[0] / ROW_LEN;          // 16384
    const int n_blocks = n_rows / ROWS_PER_CTA;        // 4096
    quant_rowwise_pipelined<<<n_blocks, THREADS>>>(x, out);
}

// round 3
// speedup vs baseline: 1.0293x; 1.0293x over previous
#include <cuda_runtime.h>
#include <cuda_bf16.h>
#include <cstdint>

#define ROW_LEN 4096
#define THREADS 256
#define V4 4   // 4096 floats / 4 per float4 / 256 threads

__global__ void __launch_bounds__(THREADS, 8)
quant_rowwise_kernel(const float* __restrict__ x, float* __restrict__ out)
{
    const size_t base = (size_t)blockIdx.x * ROW_LEN;
    const float4* __restrict__ xr   = reinterpret_cast<const float4*>(x + base);
    float4* __restrict__       outr = reinterpret_cast<float4*>(out + base);

    const int t = threadIdx.x;

    // Front-batched vector loads: 4 independent LDG.128.cs per thread.
    float4 v[V4];
#pragma unroll
    for (int k = 0; k < V4; ++k)
        v[k] = __ldcs(&xr[t + k * THREADS]);

    // Local min/max over 16 values
    float mn = v[0].x, mx = v[0].x;
#pragma unroll
    for (int k = 0; k < V4; ++k) {
        mn = fminf(mn, fminf(fminf(v[k].x, v[k].y), fminf(v[k].z, v[k].w)));
        mx = fmaxf(mx, fmaxf(fmaxf(v[k].x, v[k].y), fmaxf(v[k].z, v[k].w)));
    }

    // Warp reduce
#pragma unroll
    for (int off = 16; off > 0; off >>= 1) {
        mn = fminf(mn, __shfl_xor_sync(0xFFFFFFFFu, mn, off));
        mx = fmaxf(mx, __shfl_xor_sync(0xFFFFFFFFu, mx, off));
    }

    // Block reduce: warp leaders publish, then EVERY thread folds the 8
    // partials and computes scale/zp redundantly — only ONE barrier total.
    __shared__ float smn[8], smx[8];
    const int wid = t >> 5;
    const int lid = t & 31;
    if (lid == 0) { smn[wid] = mn; smx[wid] = mx; }
    __syncthreads();

    float bmn = smn[0], bmx = smx[0];
#pragma unroll
    for (int i = 1; i < 8; ++i) {
        bmn = fminf(bmn, smn[i]);
        bmx = fmaxf(bmx, smx[i]);
    }
    float scale = (bmx - bmn) * (1.0f / 255.0f);
    scale = fminf(fmaxf(scale, 1e-5f), 1e4f);
    float zp = -bmn / scale;
    zp = fminf(fmaxf(zp, -1e4f), 1e4f);
    const float inv = 1.0f / scale;

    // Fake quant-dequant, streaming vector stores
#pragma unroll
    for (int k = 0; k < V4; ++k) {
        float4 r;
        float q;
        q = rintf(v[k].x * inv) + zp; q = fminf(fmaxf(q, 0.0f), 255.0f); r.x = (q - zp) * scale;
        q = rintf(v[k].y * inv) + zp; q = fminf(fmaxf(q, 0.0f), 255.0f); r.y = (q - zp) * scale;
        q = rintf(v[k].z * inv) + zp; q = fminf(fmaxf(q, 0.0f), 255.0f); r.z = (q - zp) * scale;
        q = rintf(v[k].w * inv) + zp; q = fminf(fmaxf(q, 0.0f), 255.0f); r.w = (q - zp) * scale;
        __stcs(&outr[t + k * THREADS], r);
    }
}

extern "C" void kernel_launch(void* const* d_in, const int* in_sizes, int n_in,
                              void* d_out, int out_size)
{
    const float* x = (const float*)d_in[0];
    float* out = (float*)d_out;
    const int n_rows = in_sizes[0] / ROW_LEN;   // 16384
    quant_rowwise_kernel<<<n_rows, THREADS>>>(x, out);
}